// round 4
// baseline (speedup 1.0000x reference)
#include <cuda_runtime.h>

#define TW 32
#define TH 8
#define XS 37          // padded x-stride (34 used) -> conflict-free LDS
#define YS 10          // TH + 2
#define C_IN 16
#define F_OUT 64
#define IMG 512

__constant__ float c_weights[3 * 3 * C_IN * F_OUT];   // 9216 floats = 36 KB

__global__ __launch_bounds__(256, 2)
void snn_conv_kernel(const float* __restrict__ in,
                     const float* __restrict__ oldp,
                     float* __restrict__ spikes,
                     float* __restrict__ newp)
{
    __shared__ float s_in[C_IN][YS][XS];   // 23680 B

    const int tid = threadIdx.x;
    const int x0 = blockIdx.x * TW;
    const int y0 = blockIdx.y * TH;

    // ---- cooperative input-tile load: NHWC gmem -> planar [c][y][x] smem ----
    {
        const int c4 = tid & 3;          // which float4 of the 16 channels
        const int cb = c4 * 4;
        for (int p = tid >> 2; p < YS * 34; p += 64) {
            const int y = p / 34;
            const int x = p - y * 34;
            const int gy = y0 + y - 1;
            const int gx = x0 + x - 1;
            float4 v = make_float4(0.f, 0.f, 0.f, 0.f);
            if (gy >= 0 && gy < IMG && gx >= 0 && gx < IMG) {
                v = *(const float4*)&in[(((size_t)gy * IMG + gx) * C_IN) + cb];
            }
            s_in[cb + 0][y][x] = v.x;
            s_in[cb + 1][y][x] = v.y;
            s_in[cb + 2][y][x] = v.z;
            s_in[cb + 3][y][x] = v.w;
        }
    }
    __syncthreads();

    // ---- thread mapping: warp -> uniform channel-group, lanes -> pixels ----
    const int w    = tid >> 5;
    const int lane = tid & 31;
    const int cg   = w & 3;                       // uniform within warp -> LDC broadcast
    const int g    = ((w >> 2) << 5) + lane;      // 0..63 pixel-group id
    const int row  = g >> 3;                      // 0..7
    const int xoff = (g & 7) * 4;                 // 0,4,...,28

    float acc[4][16];
    #pragma unroll
    for (int i = 0; i < 4; i++)
        #pragma unroll
        for (int j = 0; j < 16; j++) acc[i][j] = 0.f;

    #pragma unroll 1
    for (int ky = 0; ky < 3; ky++) {
        #pragma unroll 1
        for (int kx = 0; kx < 3; kx++) {
            const int yy = row + ky;
            const int xx = xoff + kx;
            const float* wp = &c_weights[(ky * 3 + kx) * C_IN * F_OUT + cg * 16];
            #pragma unroll
            for (int c = 0; c < C_IN; c++) {
                float wv[16];
                *(float4*)&wv[0]  = *(const float4*)(wp + c * F_OUT + 0);
                *(float4*)&wv[4]  = *(const float4*)(wp + c * F_OUT + 4);
                *(float4*)&wv[8]  = *(const float4*)(wp + c * F_OUT + 8);
                *(float4*)&wv[12] = *(const float4*)(wp + c * F_OUT + 12);
                float iv[4];
                iv[0] = s_in[c][yy][xx + 0];
                iv[1] = s_in[c][yy][xx + 1];
                iv[2] = s_in[c][yy][xx + 2];
                iv[3] = s_in[c][yy][xx + 3];
                #pragma unroll
                for (int pxi = 0; pxi < 4; pxi++)
                    #pragma unroll
                    for (int f = 0; f < 16; f++)
                        acc[pxi][f] = fmaf(iv[pxi], wv[f], acc[pxi][f]);
            }
        }
    }

    // ---- epilogue: add old potential, threshold -> spike + reset ----
    const int gy = y0 + row;
    #pragma unroll
    for (int pxi = 0; pxi < 4; pxi++) {
        const int gx = x0 + xoff + pxi;
        const size_t base = (((size_t)gy * IMG + gx) * F_OUT) + cg * 16;
        #pragma unroll
        for (int q = 0; q < 4; q++) {
            float4 op = *(const float4*)&oldp[base + q * 4];
            float t0 = acc[pxi][q * 4 + 0] + op.x;
            float t1 = acc[pxi][q * 4 + 1] + op.y;
            float t2 = acc[pxi][q * 4 + 2] + op.z;
            float t3 = acc[pxi][q * 4 + 3] + op.w;
            float4 sv, nv;
            sv.x = (t0 >= 1.f) ? 1.f : 0.f;  nv.x = (t0 >= 1.f) ? 0.f : t0;
            sv.y = (t1 >= 1.f) ? 1.f : 0.f;  nv.y = (t1 >= 1.f) ? 0.f : t1;
            sv.z = (t2 >= 1.f) ? 1.f : 0.f;  nv.z = (t2 >= 1.f) ? 0.f : t2;
            sv.w = (t3 >= 1.f) ? 1.f : 0.f;  nv.w = (t3 >= 1.f) ? 0.f : t3;
            *(float4*)&spikes[base + q * 4] = sv;
            if (newp) *(float4*)&newp[base + q * 4] = nv;
        }
    }
}

extern "C" void kernel_launch(void* const* d_in, const int* in_sizes, int n_in,
                              void* d_out, int out_size)
{
    const float* in   = (const float*)d_in[0];   // (1,512,512,16)
    const float* wts  = (const float*)d_in[1];   // (3,3,16,64)
    const float* oldp = (const float*)d_in[2];   // (1,512,512,64)
    float* out = (float*)d_out;

    const long long N = (long long)IMG * IMG * F_OUT;   // 16,777,216
    float* spikes = out;
    float* newp   = ((long long)out_size >= 2 * N) ? (out + N) : nullptr;

    // weights -> constant memory (device-to-device async memcpy: capture-safe)
    cudaMemcpyToSymbolAsync(c_weights, wts, 3 * 3 * C_IN * F_OUT * sizeof(float),
                            0, cudaMemcpyDeviceToDevice, 0);

    dim3 grid(IMG / TW, IMG / TH);   // (16, 64)
    snn_conv_kernel<<<grid, 256>>>(in, oldp, spikes, newp);
}

// round 5
// speedup vs baseline: 1.1142x; 1.1142x over previous
#include <cuda_runtime.h>

#define TW 32
#define TH 8
#define XS 37          // padded x-stride (34 used) -> conflict-free LDS
#define YS 10          // TH + 2
#define C_IN 16
#define F_OUT 64
#define IMG 512

typedef unsigned long long u64;

__constant__ float c_weights[3 * 3 * C_IN * F_OUT];   // 9216 floats = 36 KB

__device__ __forceinline__ u64 ffma2(u64 a, u64 b, u64 c) {
    u64 d;
    asm("fma.rn.f32x2 %0, %1, %2, %3;" : "=l"(d) : "l"(a), "l"(b), "l"(c));
    return d;
}

__device__ __forceinline__ u64 bcast2(float v) {
    u64 d;
    unsigned int r = __float_as_uint(v);
    asm("mov.b64 %0, {%1, %1};" : "=l"(d) : "r"(r));
    return d;
}

__global__ __launch_bounds__(256, 2)
void snn_conv_kernel(const float* __restrict__ in,
                     const float* __restrict__ oldp,
                     float* __restrict__ spikes,
                     float* __restrict__ newp)
{
    __shared__ float s_in[C_IN][YS][XS];   // 23680 B

    const int tid = threadIdx.x;
    const int x0 = blockIdx.x * TW;
    const int y0 = blockIdx.y * TH;

    // ---- cooperative input-tile load: NHWC gmem -> planar [c][y][x] smem ----
    {
        const int c4 = tid & 3;          // which float4 of the 16 channels
        const int cb = c4 * 4;
        for (int p = tid >> 2; p < YS * 34; p += 64) {
            const int y = p / 34;
            const int x = p - y * 34;
            const int gy = y0 + y - 1;
            const int gx = x0 + x - 1;
            float4 v = make_float4(0.f, 0.f, 0.f, 0.f);
            if (gy >= 0 && gy < IMG && gx >= 0 && gx < IMG) {
                v = *(const float4*)&in[(((size_t)gy * IMG + gx) * C_IN) + cb];
            }
            s_in[cb + 0][y][x] = v.x;
            s_in[cb + 1][y][x] = v.y;
            s_in[cb + 2][y][x] = v.z;
            s_in[cb + 3][y][x] = v.w;
        }
    }
    __syncthreads();

    // ---- thread mapping: warp -> uniform channel-group, lanes -> pixels ----
    const int w    = tid >> 5;
    const int lane = tid & 31;
    const int cg   = w & 3;                       // uniform within warp
    const int g    = ((w >> 2) << 5) + lane;      // 0..63 pixel-group id
    const int row  = g >> 3;                      // 0..7
    const int xoff = (g & 7) * 4;                 // 0,4,...,28

    // packed accumulators: acc2[pxi][fp] holds (f = 2*fp, f = 2*fp+1)
    u64 acc2[4][8];
    #pragma unroll
    for (int i = 0; i < 4; i++)
        #pragma unroll
        for (int j = 0; j < 8; j++) acc2[i][j] = 0ULL;

    #pragma unroll 1
    for (int ky = 0; ky < 3; ky++) {
        #pragma unroll 1
        for (int kx = 0; kx < 3; kx++) {
            const int yy = row + ky;
            const int xx = xoff + kx;
            const float* wp = &c_weights[(ky * 3 + kx) * C_IN * F_OUT + cg * 16];
            #pragma unroll
            for (int c = 0; c < C_IN; c++) {
                // 16 consecutive f-weights = 8 packed pairs; LDC.128-friendly
                u64 wv2[8];
                const ulonglong2* w64 = (const ulonglong2*)(wp + c * F_OUT);
                ulonglong2 q0 = w64[0];
                ulonglong2 q1 = w64[1];
                ulonglong2 q2 = w64[2];
                ulonglong2 q3 = w64[3];
                wv2[0] = q0.x; wv2[1] = q0.y;
                wv2[2] = q1.x; wv2[3] = q1.y;
                wv2[4] = q2.x; wv2[5] = q2.y;
                wv2[6] = q3.x; wv2[7] = q3.y;

                u64 iv2[4];
                iv2[0] = bcast2(s_in[c][yy][xx + 0]);
                iv2[1] = bcast2(s_in[c][yy][xx + 1]);
                iv2[2] = bcast2(s_in[c][yy][xx + 2]);
                iv2[3] = bcast2(s_in[c][yy][xx + 3]);

                #pragma unroll
                for (int pxi = 0; pxi < 4; pxi++)
                    #pragma unroll
                    for (int fp = 0; fp < 8; fp++)
                        acc2[pxi][fp] = ffma2(iv2[pxi], wv2[fp], acc2[pxi][fp]);
            }
        }
    }

    // ---- epilogue: add old potential, threshold -> spike + reset ----
    const int gy = y0 + row;
    #pragma unroll
    for (int pxi = 0; pxi < 4; pxi++) {
        const int gx = x0 + xoff + pxi;
        const size_t base = (((size_t)gy * IMG + gx) * F_OUT) + cg * 16;
        const float* af = (const float*)acc2[pxi];   // af[2*fp+h] == f index 2*fp+h
        #pragma unroll
        for (int q = 0; q < 4; q++) {
            float4 op = *(const float4*)&oldp[base + q * 4];
            float t0 = af[q * 4 + 0] + op.x;
            float t1 = af[q * 4 + 1] + op.y;
            float t2 = af[q * 4 + 2] + op.z;
            float t3 = af[q * 4 + 3] + op.w;
            float4 sv, nv;
            sv.x = (t0 >= 1.f) ? 1.f : 0.f;  nv.x = (t0 >= 1.f) ? 0.f : t0;
            sv.y = (t1 >= 1.f) ? 1.f : 0.f;  nv.y = (t1 >= 1.f) ? 0.f : t1;
            sv.z = (t2 >= 1.f) ? 1.f : 0.f;  nv.z = (t2 >= 1.f) ? 0.f : t2;
            sv.w = (t3 >= 1.f) ? 1.f : 0.f;  nv.w = (t3 >= 1.f) ? 0.f : t3;
            *(float4*)&spikes[base + q * 4] = sv;
            if (newp) *(float4*)&newp[base + q * 4] = nv;
        }
    }
}

extern "C" void kernel_launch(void* const* d_in, const int* in_sizes, int n_in,
                              void* d_out, int out_size)
{
    const float* in   = (const float*)d_in[0];   // (1,512,512,16)
    const float* wts  = (const float*)d_in[1];   // (3,3,16,64)
    const float* oldp = (const float*)d_in[2];   // (1,512,512,64)
    float* out = (float*)d_out;

    const long long N = (long long)IMG * IMG * F_OUT;   // 16,777,216
    float* spikes = out;
    float* newp   = ((long long)out_size >= 2 * N) ? (out + N) : nullptr;

    // weights -> constant memory (device-to-device async memcpy: capture-safe)
    cudaMemcpyToSymbolAsync(c_weights, wts, 3 * 3 * C_IN * F_OUT * sizeof(float),
                            0, cudaMemcpyDeviceToDevice, 0);

    dim3 grid(IMG / TW, IMG / TH);   // (16, 64)
    snn_conv_kernel<<<grid, 256>>>(in, oldp, spikes, newp);
}